// round 14
// baseline (speedup 1.0000x reference)
#include <cuda_runtime.h>
#include <cuda_fp16.h>

// FWHT-4096 fp32. PERSISTENT kernel: 740 CTAs (148 SM x 5), grid-stride over
// 4096 row-pairs. 256 threads/CTA, 2 rows/iter packed as __half2 in smem.
// Radix-16 x 3 rounds, single swizzled layout S1, in-place round 2,
// DOUBLE-BUFFERED exchange (2 x 16KB) -> still only 2 barriers per iteration,
// and iteration n+1's loads/stores overlap iteration n's tail.
// S1(e): bits2-3 ^= (e>>5)&3, bit4 ^= (e>>8)&1  (conflict-free, all passes).
// fp16 exchange roundoff ~3e-4 (threshold 1e-3).

#define FWHT_N  4096
#define TPB     256
#define NPAIRS  4096
#define GRIDSZ  740     // 148 SMs x 5 resident CTAs

__device__ __forceinline__ void butterfly16(float v[16]) {
#pragma unroll
    for (int b = 1; b < 16; b <<= 1) {
#pragma unroll
        for (int k = 0; k < 16; k++) {
            if (!(k & b)) {
                float a = v[k];
                float c = v[k | b];
                v[k]     = a + c;
                v[k | b] = a - c;
            }
        }
    }
}

__global__ __launch_bounds__(TPB)
void QHadamard_40243843564239_kernel(const float* __restrict__ x,
                                     float* __restrict__ out) {
    __shared__ __half2 s[2][FWHT_N];   // 32 KB, double-buffered

    const int t = threadIdx.x;
    const int i = t & 15;
    const int w = t >> 4;
    const int wbit = w & 1;

    // Hoisted per-thread constants
    const int x1_tp   = 4 * (t ^ ((t >> 4) & 1));
    const int x1_swz  = (t >> 1) & 3;
    const int r2_ilo  = i & 3;
    const int r2_ihi  = i >> 2;
    const int r2_base = 256 * w;
    const int r3_lo   = (t & 3) + ((((t >> 2) & 3) ^ ((t >> 5) & 3)) << 2);
    const int r3_b4   = (t >> 4) & 1;
    const int r3_hi   = (t & ~31);

    int buf = 0;

    for (int pair = blockIdx.x; pair < NPAIRS; pair += GRIDSZ, buf ^= 1) {
        __half2* __restrict__ sb = s[buf];

        const size_t row0 = (size_t)pair * 2;
        const float* __restrict__ xin0  = x   + row0 * FWHT_N;
        const float* __restrict__ xin1  = xin0 + FWHT_N;
        float* __restrict__       yout0 = out + row0 * FWHT_N;
        float* __restrict__       yout1 = yout0 + FWHT_N;

        float v0[16], v1[16];

        // ---- Round 1: bits 0..3 in regs. e = 16t + k. 8x LDG.128 batched. ----
        {
            const float4* __restrict__ a4 = reinterpret_cast<const float4*>(xin0 + 16 * t);
            const float4* __restrict__ b4 = reinterpret_cast<const float4*>(xin1 + 16 * t);
            float4 fa[4], fb[4];
#pragma unroll
            for (int q = 0; q < 4; q++) fa[q] = a4[q];
#pragma unroll
            for (int q = 0; q < 4; q++) fb[q] = b4[q];
#pragma unroll
            for (int q = 0; q < 4; q++) {
                v0[4*q+0] = fa[q].x; v0[4*q+1] = fa[q].y; v0[4*q+2] = fa[q].z; v0[4*q+3] = fa[q].w;
                v1[4*q+0] = fb[q].x; v1[4*q+1] = fb[q].y; v1[4*q+2] = fb[q].z; v1[4*q+3] = fb[q].w;
            }
        }
        butterfly16(v0);
        butterfly16(v1);

        // ---- X1 write: 4x STS.128 into buffer `buf`. ----
        {
            uint4* s16 = reinterpret_cast<uint4*>(sb);
#pragma unroll
            for (int q = 0; q < 4; q++) {
                __half2 h0 = __floats2half2_rn(v0[4*q+0], v1[4*q+0]);
                __half2 h1 = __floats2half2_rn(v0[4*q+1], v1[4*q+1]);
                __half2 h2 = __floats2half2_rn(v0[4*q+2], v1[4*q+2]);
                __half2 h3 = __floats2half2_rn(v0[4*q+3], v1[4*q+3]);
                uint4 u;
                u.x = *reinterpret_cast<unsigned*>(&h0);
                u.y = *reinterpret_cast<unsigned*>(&h1);
                u.z = *reinterpret_cast<unsigned*>(&h2);
                u.w = *reinterpret_cast<unsigned*>(&h3);
                s16[x1_tp + (q ^ x1_swz)] = u;
            }
        }
        __syncthreads();

        // ---- Round 2: bits 4..7 in regs, in-place read/butterfly/write. ----
        {
#pragma unroll
            for (int j = 0; j < 16; j++) {
                const int idx = r2_ilo + ((r2_ihi ^ ((j >> 1) & 3)) << 2)
                              + ((j ^ wbit) << 4) + r2_base;
                float2 f = __half22float2(sb[idx]);
                v0[j] = f.x;
                v1[j] = f.y;
            }
            butterfly16(v0);
            butterfly16(v1);
#pragma unroll
            for (int j = 0; j < 16; j++) {
                const int idx = r2_ilo + ((r2_ihi ^ ((j >> 1) & 3)) << 2)
                              + ((j ^ wbit) << 4) + r2_base;
                sb[idx] = __floats2half2_rn(v0[j], v1[j]);
            }
        }
        __syncthreads();

        // ---- Round 3: bits 8..11 in regs. e = t + 256k (S1 layout). ----
#pragma unroll
        for (int k = 0; k < 16; k++) {
            const int idx = r3_lo + ((r3_b4 ^ (k & 1)) << 4) + r3_hi + (k << 8);
            float2 f = __half22float2(sb[idx]);
            v0[k] = f.x;
            v1[k] = f.y;
        }
        butterfly16(v0);
        butterfly16(v1);

        // ---- Store: coalesced streaming STG.32 per row (evict-first). ----
        const float scale = 0.015625f;   // 1/sqrt(4096)
#pragma unroll
        for (int k = 0; k < 16; k++) {
            __stcs(&yout0[t + 256 * k], v0[k] * scale);
            __stcs(&yout1[t + 256 * k], v1[k] * scale);
        }
        // Next iteration writes s[buf^1]; safety via the two barriers above.
    }
}

extern "C" void kernel_launch(void* const* d_in, const int* in_sizes, int n_in,
                              void* d_out, int out_size) {
    const float* x = (const float*)d_in[0];
    float* out = (float*)d_out;
    QHadamard_40243843564239_kernel<<<GRIDSZ, TPB>>>(x, out);
}

// round 15
// speedup vs baseline: 1.0406x; 1.0406x over previous
#include <cuda_runtime.h>
#include <cuda_fp16.h>

// FWHT-4096 fp32. PERSISTENT: 740 CTAs (148 SM x 5), grid-stride over 4096
// row-pairs. 256 thr/CTA, 2 rows/iter packed as __half2 in ONE 16KB smem
// buffer; 3 barriers/iter (3rd protects write-after-read across iterations).
// __launch_bounds__(256,5) pins regs <=51 so 5 CTAs/SM stay resident (the
// R14 persistent attempt died at 64 regs -> 4 CTAs). Index math recomputed
// per iter (ALU has headroom), nothing hoisted.
// S1(e): bits2-3 ^= (e>>5)&3, bit4 ^= (e>>8)&1  (conflict-free all passes).
// fp16 exchange roundoff ~3e-4 (threshold 1e-3).

#define FWHT_N  4096
#define TPB     256
#define NPAIRS  4096
#define GRIDSZ  740

__device__ __forceinline__ void butterfly16(float v[16]) {
#pragma unroll
    for (int b = 1; b < 16; b <<= 1) {
#pragma unroll
        for (int k = 0; k < 16; k++) {
            if (!(k & b)) {
                float a = v[k];
                float c = v[k | b];
                v[k]     = a + c;
                v[k | b] = a - c;
            }
        }
    }
}

__global__ __launch_bounds__(TPB, 5)
void QHadamard_40243843564239_kernel(const float* __restrict__ x,
                                     float* __restrict__ out) {
    __shared__ __half2 s[FWHT_N];   // 16 KB, single buffer

    const int t = threadIdx.x;

    for (int pair = blockIdx.x; pair < NPAIRS; pair += GRIDSZ) {
        const float* __restrict__ xin0  = x   + (size_t)pair * (2 * FWHT_N);
        const float* __restrict__ xin1  = xin0 + FWHT_N;
        float* __restrict__       yout0 = out + (size_t)pair * (2 * FWHT_N);
        float* __restrict__       yout1 = yout0 + FWHT_N;

        float v0[16], v1[16];

        // ---- Round 1: bits 0..3 in regs. e = 16t + k. 8x LDG.128 batched. ----
        {
            const float4* __restrict__ a4 = reinterpret_cast<const float4*>(xin0 + 16 * t);
            const float4* __restrict__ b4 = reinterpret_cast<const float4*>(xin1 + 16 * t);
            float4 fa[4], fb[4];
#pragma unroll
            for (int q = 0; q < 4; q++) fa[q] = a4[q];
#pragma unroll
            for (int q = 0; q < 4; q++) fb[q] = b4[q];
#pragma unroll
            for (int q = 0; q < 4; q++) {
                v0[4*q+0] = fa[q].x; v0[4*q+1] = fa[q].y; v0[4*q+2] = fa[q].z; v0[4*q+3] = fa[q].w;
                v1[4*q+0] = fb[q].x; v1[4*q+1] = fb[q].y; v1[4*q+2] = fb[q].z; v1[4*q+3] = fb[q].w;
            }
        }
        butterfly16(v0);
        butterfly16(v1);

        // ---- X1 write: 4x STS.128. unit = 4*(t ^ ((t>>4)&1)) + (q ^ ((t>>1)&3)). ----
        {
            uint4* s16 = reinterpret_cast<uint4*>(s);
#pragma unroll
            for (int q = 0; q < 4; q++) {
                __half2 h0 = __floats2half2_rn(v0[4*q+0], v1[4*q+0]);
                __half2 h1 = __floats2half2_rn(v0[4*q+1], v1[4*q+1]);
                __half2 h2 = __floats2half2_rn(v0[4*q+2], v1[4*q+2]);
                __half2 h3 = __floats2half2_rn(v0[4*q+3], v1[4*q+3]);
                uint4 u;
                u.x = *reinterpret_cast<unsigned*>(&h0);
                u.y = *reinterpret_cast<unsigned*>(&h1);
                u.z = *reinterpret_cast<unsigned*>(&h2);
                u.w = *reinterpret_cast<unsigned*>(&h3);
                s16[4 * (t ^ ((t >> 4) & 1)) + (q ^ ((t >> 1) & 3))] = u;
            }
        }
        __syncthreads();

        // ---- Round 2: bits 4..7 in regs. e = i + 16j + 256w, in place. ----
        {
            const int i = t & 15;
            const int w = t >> 4;
#pragma unroll
            for (int j = 0; j < 16; j++) {
                const int idx = (i & 3) + (((i >> 2) ^ ((j >> 1) & 3)) << 2)
                              + ((j ^ (w & 1)) << 4) + 256 * w;
                float2 f = __half22float2(s[idx]);
                v0[j] = f.x;
                v1[j] = f.y;
            }
            butterfly16(v0);
            butterfly16(v1);
#pragma unroll
            for (int j = 0; j < 16; j++) {
                const int idx = (i & 3) + (((i >> 2) ^ ((j >> 1) & 3)) << 2)
                              + ((j ^ (w & 1)) << 4) + 256 * w;
                s[idx] = __floats2half2_rn(v0[j], v1[j]);
            }
        }
        __syncthreads();

        // ---- Round 3: bits 8..11 in regs. e = t + 256k (S1 layout). ----
#pragma unroll
        for (int k = 0; k < 16; k++) {
            const int idx = (t & 3) + ((((t >> 2) & 3) ^ ((t >> 5) & 3)) << 2)
                          + ((((t >> 4) & 1) ^ (k & 1)) << 4) + (t & ~31) + (k << 8);
            float2 f = __half22float2(s[idx]);
            v0[k] = f.x;
            v1[k] = f.y;
        }
        butterfly16(v0);
        butterfly16(v1);

        // ---- Store: coalesced streaming STG.32 per row (evict-first). ----
#pragma unroll
        for (int k = 0; k < 16; k++) {
            __stcs(&yout0[t + 256 * k], v0[k] * 0.015625f);
            __stcs(&yout1[t + 256 * k], v1[k] * 0.015625f);
        }

        // Protect next iteration's X1 writes against this iter's R3 reads.
        __syncthreads();
    }
}

extern "C" void kernel_launch(void* const* d_in, const int* in_sizes, int n_in,
                              void* d_out, int out_size) {
    const float* x = (const float*)d_in[0];
    float* out = (float*)d_out;
    QHadamard_40243843564239_kernel<<<GRIDSZ, TPB>>>(x, out);
}